// round 12
// baseline (speedup 1.0000x reference)
#include <cuda_runtime.h>
#include <cstdint>

#define BATCH 8
#define HALFB 4
#define EMBD  1024
#define CIND  512
#define NTOK  1024
#define SEQL  1024

// ---------------- scratch (device globals; allocation-free) ----------------
__device__ float g_xT [(size_t)BATCH * NTOK * CIND];  // x^T, tf32-rounded
__device__ float g_Ct [(size_t)BATCH * SEQL * EMBD];  // rounded content
__device__ float g_Zt [(size_t)BATCH * SEQL * CIND];  // Zt[s][c] = Ct·Mz (rounded)
__device__ float g_beta[(size_t)BATCH * SEQL];        // scale * Ct·bk  (fp32)
__device__ float g_aR [(size_t)BATCH * NTOK * SEQL];  // rounded copy of att
__device__ float g_Ut [(size_t)BATCH * CIND * SEQL];  // Ut[c][s]
__device__ float g_Wq2[EMBD * EMBD];                  // rounded Wq
__device__ float g_Wkt[EMBD * EMBD];                  // Wk^T rounded: [e][e']
__device__ float g_Wit[CIND * EMBD];                  // W_in^T rounded
__device__ float g_WqiT[CIND * EMBD];                 // (Wq·W_in)^T : [c][e']
__device__ float g_Mz [CIND * EMBD];                  // Mz[c][e] = Wqi^T·Wk
__device__ float g_bq [EMBD];                         // Wq·b_in (fp32)
__device__ float g_bk [EMBD];                         // Wk^T·bq (fp32)
__device__ float g_Wo2[CIND * EMBD];                  // rounded W_out
__device__ float g_Wvt[EMBD * EMBD];                  // Wv^T rounded
__device__ float g_Wvo[CIND * EMBD];                  // folded W_out·Wv

// ---------------- helpers ----------------
__device__ __forceinline__ uint32_t smem_u32(const void* p) {
    uint32_t a;
    asm("{ .reg .u64 t; cvta.to.shared.u64 t, %1; cvt.u32.u64 %0, t; }" : "=r"(a) : "l"(p));
    return a;
}
__device__ __forceinline__ uint32_t f2tf(float x) {
    uint32_t r; asm("cvt.rna.tf32.f32 %0, %1;" : "=r"(r) : "f"(x)); return r;
}
__device__ __forceinline__ float rtf(float x) { return __uint_as_float(f2tf(x)); }

#define CP_ASYNC16(dst, src) \
    asm volatile("cp.async.cg.shared.global.L2::128B [%0], [%1], 16;" \
                 :: "r"(dst), "l"(src) : "memory")
#define CP_COMMIT() asm volatile("cp.async.commit_group;" ::: "memory")
#define CP_WAIT1()  asm volatile("cp.async.wait_group 1;" ::: "memory")

__device__ __forceinline__ void ldsm_x4(uint32_t* r, uint32_t a) {
    asm volatile("ldmatrix.sync.aligned.m8n8.x4.shared.b16 {%0,%1,%2,%3}, [%4];"
                 : "=r"(r[0]), "=r"(r[1]), "=r"(r[2]), "=r"(r[3]) : "r"(a));
}
__device__ __forceinline__ void ldsm_x2(uint32_t* r, uint32_t a) {
    asm volatile("ldmatrix.sync.aligned.m8n8.x2.shared.b16 {%0,%1}, [%2];"
                 : "=r"(r[0]), "=r"(r[1]) : "r"(a));
}
__device__ __forceinline__ void mma_tf32(float* d, const uint32_t* a, const uint32_t* b) {
    asm volatile(
        "mma.sync.aligned.m16n8k8.row.col.f32.tf32.tf32.f32 "
        "{%0,%1,%2,%3}, {%4,%5,%6,%7}, {%8,%9}, {%0,%1,%2,%3};"
        : "+f"(d[0]), "+f"(d[1]), "+f"(d[2]), "+f"(d[3])
        : "r"(a[0]), "r"(a[1]), "r"(a[2]), "r"(a[3]), "r"(b[0]), "r"(b[1]));
}

// ---------------------------------------------------------------------------
// TF32 tensor-core GEMM:  C[m][n] = alpha * sum_k A[m][k] * B[n][k] (+bias)
// A, B K-major, row stride == K, PRE-ROUNDED to tf32 in memory.
// Block tile 128x128, BK=32, 3-stage cp.async pipeline, 128 threads
// (4 warps 2x2, warp tile 64x64). Single barrier per K-chunk.
// MBIAS: 0 none, 1 row bias (per m), 2 batched col bias. RND: round C store.
// ---------------------------------------------------------------------------
#define STAGE_BYTES 32768
#define SMEM_BYTES  (3 * STAGE_BYTES)

template<int MBIAS, int RND>
__global__ __launch_bounds__(128, 2) void tc_gemm(
    const float* __restrict__ A, const float* __restrict__ B,
    float* __restrict__ C, const float* __restrict__ bias,
    int K, int ldc, size_t sA, size_t sB, size_t sC, size_t sBias, float alpha)
{
    extern __shared__ char smem[];
    const uint32_t sbase = smem_u32(smem);
    const int tid  = threadIdx.x;
    const int wid  = tid >> 5, lane = tid & 31;
    const int g = lane >> 2, t = lane & 3;
    const int m0w = (wid & 1) * 64;
    const int n0w = (wid >> 1) * 64;

    const float* Ab = A + blockIdx.z * sA + (size_t)(blockIdx.y * 128) * K;
    const float* Bb = B + blockIdx.z * sB + (size_t)(blockIdx.x * 128) * K;
    float*       Cb = C + blockIdx.z * sC + (size_t)(blockIdx.y * 128) * ldc
                        + blockIdx.x * 128;

    const int fr = tid >> 3;          // 0..15
    const int fq = tid & 7;

    auto issue = [&](int stage) {
        const uint32_t sa = sbase + (stage % 3) * STAGE_BYTES;
        const int k0 = stage * 32;
        #pragma unroll
        for (int i = 0; i < 8; i++) {
            const int r = fr + i * 16;
            const uint32_t dst = sa + r * 128 + ((fq ^ (r & 7)) << 4);
            CP_ASYNC16(dst, Ab + (size_t)r * K + k0 + fq * 4);
        }
        #pragma unroll
        for (int i = 0; i < 8; i++) {
            const int r = fr + i * 16;
            const uint32_t dst = sa + 16384 + r * 128 + ((fq ^ (r & 7)) << 4);
            CP_ASYNC16(dst, Bb + (size_t)r * K + k0 + fq * 4);
        }
    };

    const int aRow8 = (lane & 7) + ((lane >> 3) & 1) * 8;
    const int aCSel = (lane >> 4) & 1;
    uint32_t aBase[4]; int aPar[4];
    #pragma unroll
    for (int mt = 0; mt < 4; mt++) {
        const int r = m0w + mt * 16 + aRow8;
        aBase[mt] = (uint32_t)r * 128;
        aPar[mt]  = r & 7;
    }
    const int bCSel = (lane >> 3) & 1;
    uint32_t bBase[8]; int bPar[8];
    #pragma unroll
    for (int nt = 0; nt < 8; nt++) {
        const int r = n0w + nt * 8 + (lane & 7);
        bBase[nt] = 16384u + (uint32_t)r * 128;
        bPar[nt]  = r & 7;
    }

    float acc[4][8][4];
    #pragma unroll
    for (int mt = 0; mt < 4; mt++)
        #pragma unroll
        for (int nt = 0; nt < 8; nt++)
            #pragma unroll
            for (int i = 0; i < 4; i++) acc[mt][nt][i] = 0.0f;

    const int NC = K >> 5;
    issue(0); CP_COMMIT();
    issue(1); CP_COMMIT();

    for (int c = 0; c < NC; c++) {
        CP_WAIT1();
        __syncthreads();                    // single barrier per chunk
        if (c + 2 < NC) issue(c + 2);
        CP_COMMIT();

        const uint32_t stg = sbase + (c % 3) * STAGE_BYTES;

        #pragma unroll
        for (int ks = 0; ks < 4; ks++) {
            const int ca = 2 * ks + aCSel;
            const int cb = 2 * ks + bCSel;
            uint32_t a[4][4], b[8][2];
            #pragma unroll
            for (int mt = 0; mt < 4; mt++)
                ldsm_x4(a[mt], stg + aBase[mt] + (uint32_t)((ca ^ aPar[mt]) << 4));
            #pragma unroll
            for (int nt = 0; nt < 8; nt++)
                ldsm_x2(b[nt], stg + bBase[nt] + (uint32_t)((cb ^ bPar[nt]) << 4));
            #pragma unroll
            for (int mt = 0; mt < 4; mt++)
                #pragma unroll
                for (int nt = 0; nt < 8; nt++)
                    mma_tf32(acc[mt][nt], a[mt], b[nt]);
        }
    }

    #pragma unroll
    for (int mt = 0; mt < 4; mt++) {
        const int rm = blockIdx.y * 128 + m0w + mt * 16 + g;
        const float bv0 = (MBIAS == 1) ? __ldg(bias + rm)     : 0.0f;
        const float bv1 = (MBIAS == 1) ? __ldg(bias + rm + 8) : 0.0f;
        #pragma unroll
        for (int nt = 0; nt < 8; nt++) {
            const int cn = n0w + nt * 8 + t * 2;
            float cb0 = 0.0f, cb1 = 0.0f;
            if (MBIAS == 2) {
                const float* bb = bias + blockIdx.z * sBias + blockIdx.x * 128 + cn;
                cb0 = __ldg(bb);
                cb1 = __ldg(bb + 1);
            }
            float2 v0, v1;
            v0.x = alpha * acc[mt][nt][0] + bv0 + cb0;
            v0.y = alpha * acc[mt][nt][1] + bv0 + cb1;
            v1.x = alpha * acc[mt][nt][2] + bv1 + cb0;
            v1.y = alpha * acc[mt][nt][3] + bv1 + cb1;
            if (RND) {
                v0.x = rtf(v0.x); v0.y = rtf(v0.y);
                v1.x = rtf(v1.x); v1.y = rtf(v1.y);
            }
            const int r = m0w + mt * 16 + g;
            *reinterpret_cast<float2*>(&Cb[(size_t)r * ldc + cn]) = v0;
            *reinterpret_cast<float2*>(&Cb[(size_t)(r + 8) * ldc + cn]) = v1;
        }
    }
}

// ---------------------------------------------------------------------------
__global__ __launch_bounds__(256) void round_tf32(
    const float* __restrict__ in, float* __restrict__ out)
{
    const size_t i = (size_t)blockIdx.x * 256 + threadIdx.x;
    float4 v = reinterpret_cast<const float4*>(in)[i];
    v.x = rtf(v.x); v.y = rtf(v.y); v.z = rtf(v.z); v.w = rtf(v.w);
    reinterpret_cast<float4*>(out)[i] = v;
}

// ---------------------------------------------------------------------------
// Generic transpose with tf32 rounding: in (R x C) -> out (C x R)
// ---------------------------------------------------------------------------
__global__ void transpose_rnd(const float* __restrict__ in, float* __restrict__ out,
                              int R, int C)
{
    __shared__ float tb[32][33];
    const int c0 = blockIdx.x * 32, r0 = blockIdx.y * 32;
    const int tx = threadIdx.x, ty = threadIdx.y;
    #pragma unroll
    for (int j = 0; j < 32; j += 8)
        tb[ty + j][tx] = in[(size_t)(r0 + ty + j) * C + c0 + tx];
    __syncthreads();
    #pragma unroll
    for (int j = 0; j < 32; j += 8)
        out[(size_t)(c0 + ty + j) * R + r0 + tx] = rtf(tb[tx][ty + j]);
}

// ---------------------------------------------------------------------------
__global__ void transpose_x(const float* __restrict__ in, float* __restrict__ out)
{
    __shared__ float tb[32][33];
    const int n0 = blockIdx.x * 32, c0 = blockIdx.y * 32;
    const float* ib = in  + (size_t)blockIdx.z * CIND * NTOK;
    float*       ob = out + (size_t)blockIdx.z * NTOK * CIND;
    const int tx = threadIdx.x, ty = threadIdx.y;
    #pragma unroll
    for (int j = 0; j < 32; j += 8)
        tb[ty + j][tx] = ib[(size_t)(c0 + ty + j) * NTOK + n0 + tx];
    __syncthreads();
    #pragma unroll
    for (int j = 0; j < 32; j += 8)
        ob[(size_t)(n0 + ty + j) * CIND + c0 + tx] = rtf(tb[tx][ty + j]);
}

// ---------------------------------------------------------------------------
// out[r] = sum_e W[r][e] * b[e]   (fp32 GEMV, W is EMBD x EMBD)
// ---------------------------------------------------------------------------
__global__ __launch_bounds__(256) void gemv_bias(
    const float* __restrict__ W, const float* __restrict__ b, float* __restrict__ out)
{
    __shared__ float red[256];
    const int r = blockIdx.x;
    float s = 0.0f;
    for (int e = threadIdx.x; e < EMBD; e += 256)
        s += W[(size_t)r * EMBD + e] * b[e];
    red[threadIdx.x] = s;
    __syncthreads();
    for (int o = 128; o; o >>= 1) {
        if (threadIdx.x < o) red[threadIdx.x] += red[threadIdx.x + o];
        __syncthreads();
    }
    if (threadIdx.x == 0) out[r] = red[0];
}

// ---------------------------------------------------------------------------
// beta[row] = scale * sum_e M[row][e] * v[e]   (one warp per row, fp32)
// ---------------------------------------------------------------------------
__global__ __launch_bounds__(256) void beta_rows(
    const float* __restrict__ M, const float* __restrict__ v,
    float* __restrict__ beta, float scale)
{
    const int row = blockIdx.x * 8 + (threadIdx.x >> 5);
    const int lane = threadIdx.x & 31;
    const float* mr = M + (size_t)row * EMBD;
    float s = 0.0f;
    #pragma unroll 4
    for (int e = lane; e < EMBD; e += 32) s += mr[e] * v[e];
    #pragma unroll
    for (int o = 16; o; o >>= 1) s += __shfl_xor_sync(0xffffffffu, s, o);
    if (lane == 0) beta[row] = scale * s;
}

// ---------------------------------------------------------------------------
__global__ __launch_bounds__(256) void softmax_rows(
    float* __restrict__ S, float* __restrict__ SR,
    const unsigned char* __restrict__ mask)
{
    const size_t row = blockIdx.x;
    float4* p  = reinterpret_cast<float4*>(S  + row * SEQL);
    float4* pr = reinterpret_cast<float4*>(SR + row * SEQL);
    const uchar4* mp = reinterpret_cast<const uchar4*>(mask + row * SEQL);
    const int t = threadIdx.x;

    float4 v = p[t];
    uchar4 m = mp[t];
    if (m.x) v.x = -1e9f;
    if (m.y) v.y = -1e9f;
    if (m.z) v.z = -1e9f;
    if (m.w) v.w = -1e9f;

    float mx = fmaxf(fmaxf(v.x, v.y), fmaxf(v.z, v.w));
    #pragma unroll
    for (int o = 16; o; o >>= 1) mx = fmaxf(mx, __shfl_xor_sync(0xffffffffu, mx, o));
    __shared__ float sm[8];
    const int w = t >> 5;
    if ((t & 31) == 0) sm[w] = mx;
    __syncthreads();
    float rmax = sm[0];
    #pragma unroll
    for (int i = 1; i < 8; i++) rmax = fmaxf(rmax, sm[i]);

    v.x = __expf(v.x - rmax); v.y = __expf(v.y - rmax);
    v.z = __expf(v.z - rmax); v.w = __expf(v.w - rmax);

    float s = v.x + v.y + v.z + v.w;
    #pragma unroll
    for (int o = 16; o; o >>= 1) s += __shfl_xor_sync(0xffffffffu, s, o);
    __shared__ float ss[8];
    if ((t & 31) == 0) ss[w] = s;
    __syncthreads();
    float tot = 0.0f;
    #pragma unroll
    for (int i = 0; i < 8; i++) tot += ss[i];

    float inv = 1.0f / tot;
    v.x *= inv; v.y *= inv; v.z *= inv; v.w *= inv;
    p[t] = v;
    float4 r;
    r.x = rtf(v.x); r.y = rtf(v.y); r.z = rtf(v.z); r.w = rtf(v.w);
    pr[t] = r;
}

// ---------------------------------------------------------------------------
extern "C" void kernel_launch(void* const* d_in, const int* in_sizes, int n_in,
                              void* d_out, int out_size)
{
    const float* x       = (const float*)d_in[0];
    const float* content = (const float*)d_in[1];
    const unsigned char* pmask = (const unsigned char*)d_in[2];
    const float* W_in    = (const float*)d_in[3];
    const float* b_in    = (const float*)d_in[4];
    const float* Wq      = (const float*)d_in[5];
    const float* Wk      = (const float*)d_in[6];
    const float* Wv      = (const float*)d_in[7];
    const float* W_out   = (const float*)d_in[8];
    const float* b_out   = (const float*)d_in[9];

    float* out = (float*)d_out;                       // (8,512,32,32)
    float* att = out + (size_t)BATCH * CIND * NTOK;   // (8,1024,1024)

    float *xT, *Ct, *Zt, *beta, *aR, *Ut, *Wq2, *Wkt, *Wit, *WqiT, *Mz,
          *bq, *bk, *Wo2, *Wvt, *Wvo;
    cudaGetSymbolAddress((void**)&xT,   g_xT);
    cudaGetSymbolAddress((void**)&Ct,   g_Ct);
    cudaGetSymbolAddress((void**)&Zt,   g_Zt);
    cudaGetSymbolAddress((void**)&beta, g_beta);
    cudaGetSymbolAddress((void**)&aR,   g_aR);
    cudaGetSymbolAddress((void**)&Ut,   g_Ut);
    cudaGetSymbolAddress((void**)&Wq2,  g_Wq2);
    cudaGetSymbolAddress((void**)&Wkt,  g_Wkt);
    cudaGetSymbolAddress((void**)&Wit,  g_Wit);
    cudaGetSymbolAddress((void**)&WqiT, g_WqiT);
    cudaGetSymbolAddress((void**)&Mz,   g_Mz);
    cudaGetSymbolAddress((void**)&bq,   g_bq);
    cudaGetSymbolAddress((void**)&bk,   g_bk);
    cudaGetSymbolAddress((void**)&Wo2,  g_Wo2);
    cudaGetSymbolAddress((void**)&Wvt,  g_Wvt);
    cudaGetSymbolAddress((void**)&Wvo,  g_Wvo);

    cudaFuncSetAttribute(tc_gemm<0,1>, cudaFuncAttributeMaxDynamicSharedMemorySize, SMEM_BYTES);
    cudaFuncSetAttribute(tc_gemm<1,0>, cudaFuncAttributeMaxDynamicSharedMemorySize, SMEM_BYTES);
    cudaFuncSetAttribute(tc_gemm<2,0>, cudaFuncAttributeMaxDynamicSharedMemorySize, SMEM_BYTES);

    static cudaStream_t s1 = nullptr;
    static cudaEvent_t eF = nullptr, eXT = nullptr, ebq = nullptr, eWkt = nullptr,
                       eCt = nullptr, eMz = nullptr, eZall = nullptr,
                       eUt = nullptr, eE = nullptr;
    if (s1 == nullptr) {
        cudaStreamCreateWithFlags(&s1, cudaStreamNonBlocking);
        cudaEventCreateWithFlags(&eF,   cudaEventDisableTiming);
        cudaEventCreateWithFlags(&eXT,  cudaEventDisableTiming);
        cudaEventCreateWithFlags(&ebq,  cudaEventDisableTiming);
        cudaEventCreateWithFlags(&eWkt, cudaEventDisableTiming);
        cudaEventCreateWithFlags(&eCt,  cudaEventDisableTiming);
        cudaEventCreateWithFlags(&eMz,  cudaEventDisableTiming);
        cudaEventCreateWithFlags(&eZall,cudaEventDisableTiming);
        cudaEventCreateWithFlags(&eUt,  cudaEventDisableTiming);
        cudaEventCreateWithFlags(&eE,   cudaEventDisableTiming);
    }

    const size_t SE  = (size_t)SEQL * EMBD;
    const size_t NS  = (size_t)NTOK * SEQL;
    const size_t NSc = (size_t)SEQL * CIND;
    const size_t XC  = (size_t)NTOK * CIND;
    const size_t CS  = (size_t)CIND * SEQL;
    const size_t CN  = (size_t)CIND * NTOK;
    const float scale = 1.0f / 32.0f;

    // Capture legality: every cudaStreamWaitEvent is enqueued AFTER its
    // cudaEventRecord in host order.

    // ---- fork ----
    cudaEventRecord(eF, 0);
    cudaStreamWaitEvent(s1, eF, 0);

    // ======== s1 part 1: Wk^T + content round ========
    transpose_rnd<<<dim3(EMBD / 32, EMBD / 32), dim3(32, 8), 0, s1>>>(Wk, Wkt, EMBD, EMBD);
    cudaEventRecord(eWkt, s1);
    round_tf32<<<(BATCH * SE) / 1024, 256, 0, s1>>>(content, Ct);
    cudaEventRecord(eCt, s1);

    // ======== s0: prep, Mz fold, Ut ========
    transpose_x<<<dim3(NTOK / 32, CIND / 32, BATCH), dim3(32, 8)>>>(x, xT);
    cudaEventRecord(eXT, 0);
    round_tf32<<<(EMBD * EMBD) / 1024, 256>>>(Wq, Wq2);
    gemv_bias<<<EMBD, 256>>>(Wq, b_in, bq);
    cudaEventRecord(ebq, 0);
    transpose_rnd<<<dim3(CIND / 32, EMBD / 32), dim3(32, 8)>>>(W_in, Wit, EMBD, CIND);
    // WqiT[c][e'] = Wit[c][e]·Wq2[e'][e]   (M=512, N=1024, K=1024)
    tc_gemm<0,1><<<dim3(8, 4, 1), 128, SMEM_BYTES>>>(
        Wit, Wq2, WqiT, nullptr, EMBD, EMBD, 0, 0, 0, 0, 1.0f);
    cudaStreamWaitEvent(0, eWkt, 0);
    // Mz[c][e] = WqiT[c][e']·Wkt[e][e']   (M=512, N=1024, K=1024)
    tc_gemm<0,1><<<dim3(8, 4, 1), 128, SMEM_BYTES>>>(
        WqiT, Wkt, Mz, nullptr, EMBD, EMBD, 0, 0, 0, 0, 1.0f);
    cudaEventRecord(eMz, 0);
    round_tf32<<<(CIND * EMBD) / 1024, 256>>>(W_out, Wo2);
    transpose_rnd<<<dim3(EMBD / 32, EMBD / 32), dim3(32, 8)>>>(Wv, Wvt, EMBD, EMBD);
    // Wvo[c][d] = Wo2[c][e]·Wvt[d][e]
    tc_gemm<0,1><<<dim3(8, 4, 1), 128, SMEM_BYTES>>>(
        Wo2, Wvt, Wvo, nullptr, EMBD, EMBD, 0, 0, 0, 0, 1.0f);
    // Ut[c][s] = Wvo[c][d]·Ct[s][d]   (all 8 batches; needs Ct)
    cudaStreamWaitEvent(0, eCt, 0);
    tc_gemm<0,1><<<dim3(8, 4, BATCH), 128, SMEM_BYTES>>>(
        Wvo, Ct, Ut, nullptr, EMBD, SEQL, 0, SE, CS, 0, 1.0f);
    cudaEventRecord(eUt, 0);

    // ======== s1 part 2: bk, beta, Zt, half-2 tail ========
    cudaStreamWaitEvent(s1, ebq, 0);
    gemv_bias<<<EMBD, 256, 0, s1>>>(Wkt, bq, bk);       // bk[e] = Wk^T·bq
    beta_rows<<<(BATCH * SEQL) / 8, 256, 0, s1>>>(Ct, bk, beta, scale);
    cudaStreamWaitEvent(s1, eMz, 0);
    // Zt[s][c] = Ct[s][e]·Mz[c][e]   (all 8 batches; M=1024, N=512, K=1024)
    tc_gemm<0,1><<<dim3(4, 8, BATCH), 128, SMEM_BYTES, s1>>>(
        Ct, Mz, Zt, nullptr, EMBD, CIND, SE, 0, NSc, 0, 1.0f);
    cudaEventRecord(eZall, s1);
    // S half2 = scale·xT·Zt^T + beta (col bias)
    cudaStreamWaitEvent(s1, eXT, 0);
    tc_gemm<2,0><<<dim3(8, 8, HALFB), 128, SMEM_BYTES, s1>>>(
        xT + (size_t)HALFB * XC, Zt + (size_t)HALFB * NSc,
        att + (size_t)HALFB * NS, beta + (size_t)HALFB * SEQL,
        CIND, SEQL, XC, NSc, NS, SEQL, scale);
    softmax_rows<<<HALFB * NTOK, 256, 0, s1>>>(
        att + (size_t)HALFB * NS, aR + (size_t)HALFB * NS,
        pmask + (size_t)HALFB * NS);
    cudaStreamWaitEvent(s1, eUt, 0);
    tc_gemm<1,0><<<dim3(8, 4, HALFB), 128, SMEM_BYTES, s1>>>(
        Ut + (size_t)HALFB * CS, aR + (size_t)HALFB * NS,
        out + (size_t)HALFB * CN, b_out, SEQL, NTOK, CS, NS, CN, 0, 1.0f);

    // ======== s0: half-1 tail ========
    cudaStreamWaitEvent(0, eZall, 0);
    tc_gemm<2,0><<<dim3(8, 8, HALFB), 128, SMEM_BYTES>>>(
        xT, Zt, att, beta, CIND, SEQL, XC, NSc, NS, SEQL, scale);
    softmax_rows<<<HALFB * NTOK, 256>>>(att, aR, pmask);
    tc_gemm<1,0><<<dim3(8, 4, HALFB), 128, SMEM_BYTES>>>(
        Ut, aR, out, b_out, SEQL, NTOK, CS, NS, CN, 0, 1.0f);

    // ---- join ----
    cudaEventRecord(eE, s1);
    cudaStreamWaitEvent(0, eE, 0);
}

// round 14
// speedup vs baseline: 1.1277x; 1.1277x over previous
#include <cuda_runtime.h>
#include <cstdint>

#define BATCH 8
#define QB    2                      // batches per quarter
#define EMBD  1024
#define CIND  512
#define NTOK  1024
#define SEQL  1024

// ---------------- scratch (device globals; allocation-free) ----------------
__device__ float g_xT [(size_t)BATCH * NTOK * CIND];  // x^T, tf32-rounded
__device__ float g_Ct [(size_t)BATCH * SEQL * EMBD];  // rounded content
__device__ float g_Zt [(size_t)BATCH * SEQL * CIND];  // Zt[s][c] = Ct·Mz (rounded)
__device__ float g_beta[(size_t)BATCH * SEQL];        // scale * Ct·bk  (fp32)
__device__ float g_aR [(size_t)BATCH * NTOK * SEQL];  // rounded copy of att
__device__ float g_Ut [(size_t)BATCH * CIND * SEQL];  // Ut[c][s]
__device__ float g_Wq2[EMBD * EMBD];                  // rounded Wq
__device__ float g_Wkt[EMBD * EMBD];                  // Wk^T rounded: [e][e']
__device__ float g_Wit[CIND * EMBD];                  // W_in^T rounded
__device__ float g_WqiT[CIND * EMBD];                 // (Wq·W_in)^T : [c][e']
__device__ float g_Mz [CIND * EMBD];                  // Mz[c][e] = Wqi^T·Wk
__device__ float g_bq [EMBD];                         // Wq·b_in (fp32)
__device__ float g_bk [EMBD];                         // Wk^T·bq (fp32)
__device__ float g_Wo2[CIND * EMBD];                  // rounded W_out
__device__ float g_Wvt[EMBD * EMBD];                  // Wv^T rounded
__device__ float g_Wvo[CIND * EMBD];                  // folded W_out·Wv

// ---------------- helpers ----------------
__device__ __forceinline__ uint32_t smem_u32(const void* p) {
    uint32_t a;
    asm("{ .reg .u64 t; cvta.to.shared.u64 t, %1; cvt.u32.u64 %0, t; }" : "=r"(a) : "l"(p));
    return a;
}
__device__ __forceinline__ uint32_t f2tf(float x) {
    uint32_t r; asm("cvt.rna.tf32.f32 %0, %1;" : "=r"(r) : "f"(x)); return r;
}
__device__ __forceinline__ float rtf(float x) { return __uint_as_float(f2tf(x)); }

#define CP_ASYNC16(dst, src) \
    asm volatile("cp.async.cg.shared.global.L2::128B [%0], [%1], 16;" \
                 :: "r"(dst), "l"(src) : "memory")
#define CP_COMMIT() asm volatile("cp.async.commit_group;" ::: "memory")
#define CP_WAIT1()  asm volatile("cp.async.wait_group 1;" ::: "memory")

__device__ __forceinline__ void ldsm_x4(uint32_t* r, uint32_t a) {
    asm volatile("ldmatrix.sync.aligned.m8n8.x4.shared.b16 {%0,%1,%2,%3}, [%4];"
                 : "=r"(r[0]), "=r"(r[1]), "=r"(r[2]), "=r"(r[3]) : "r"(a));
}
__device__ __forceinline__ void ldsm_x2(uint32_t* r, uint32_t a) {
    asm volatile("ldmatrix.sync.aligned.m8n8.x2.shared.b16 {%0,%1}, [%2];"
                 : "=r"(r[0]), "=r"(r[1]) : "r"(a));
}
__device__ __forceinline__ void mma_tf32(float* d, const uint32_t* a, const uint32_t* b) {
    asm volatile(
        "mma.sync.aligned.m16n8k8.row.col.f32.tf32.tf32.f32 "
        "{%0,%1,%2,%3}, {%4,%5,%6,%7}, {%8,%9}, {%0,%1,%2,%3};"
        : "+f"(d[0]), "+f"(d[1]), "+f"(d[2]), "+f"(d[3])
        : "r"(a[0]), "r"(a[1]), "r"(a[2]), "r"(a[3]), "r"(b[0]), "r"(b[1]));
}

// ---------------------------------------------------------------------------
// TF32 tensor-core GEMM:  C[m][n] = alpha * sum_k A[m][k] * B[n][k] (+bias)
// A, B K-major, row stride == K, PRE-ROUNDED to tf32 in memory.
// Block tile 128x128, BK=32, 3-stage cp.async pipeline, 128 threads
// (4 warps 2x2, warp tile 64x64). Single barrier per K-chunk.
// MBIAS: 0 none, 1 row bias (per m), 2 batched col bias. RND: round C store.
// ---------------------------------------------------------------------------
#define STAGE_BYTES 32768
#define SMEM_BYTES  (3 * STAGE_BYTES)

template<int MBIAS, int RND>
__global__ __launch_bounds__(128, 2) void tc_gemm(
    const float* __restrict__ A, const float* __restrict__ B,
    float* __restrict__ C, const float* __restrict__ bias,
    int K, int ldc, size_t sA, size_t sB, size_t sC, size_t sBias, float alpha)
{
    extern __shared__ char smem[];
    const uint32_t sbase = smem_u32(smem);
    const int tid  = threadIdx.x;
    const int wid  = tid >> 5, lane = tid & 31;
    const int g = lane >> 2, t = lane & 3;
    const int m0w = (wid & 1) * 64;
    const int n0w = (wid >> 1) * 64;

    const float* Ab = A + blockIdx.z * sA + (size_t)(blockIdx.y * 128) * K;
    const float* Bb = B + blockIdx.z * sB + (size_t)(blockIdx.x * 128) * K;
    float*       Cb = C + blockIdx.z * sC + (size_t)(blockIdx.y * 128) * ldc
                        + blockIdx.x * 128;

    const int fr = tid >> 3;          // 0..15
    const int fq = tid & 7;

    auto issue = [&](int stage) {
        const uint32_t sa = sbase + (stage % 3) * STAGE_BYTES;
        const int k0 = stage * 32;
        #pragma unroll
        for (int i = 0; i < 8; i++) {
            const int r = fr + i * 16;
            const uint32_t dst = sa + r * 128 + ((fq ^ (r & 7)) << 4);
            CP_ASYNC16(dst, Ab + (size_t)r * K + k0 + fq * 4);
        }
        #pragma unroll
        for (int i = 0; i < 8; i++) {
            const int r = fr + i * 16;
            const uint32_t dst = sa + 16384 + r * 128 + ((fq ^ (r & 7)) << 4);
            CP_ASYNC16(dst, Bb + (size_t)r * K + k0 + fq * 4);
        }
    };

    const int aRow8 = (lane & 7) + ((lane >> 3) & 1) * 8;
    const int aCSel = (lane >> 4) & 1;
    uint32_t aBase[4]; int aPar[4];
    #pragma unroll
    for (int mt = 0; mt < 4; mt++) {
        const int r = m0w + mt * 16 + aRow8;
        aBase[mt] = (uint32_t)r * 128;
        aPar[mt]  = r & 7;
    }
    const int bCSel = (lane >> 3) & 1;
    uint32_t bBase[8]; int bPar[8];
    #pragma unroll
    for (int nt = 0; nt < 8; nt++) {
        const int r = n0w + nt * 8 + (lane & 7);
        bBase[nt] = 16384u + (uint32_t)r * 128;
        bPar[nt]  = r & 7;
    }

    float acc[4][8][4];
    #pragma unroll
    for (int mt = 0; mt < 4; mt++)
        #pragma unroll
        for (int nt = 0; nt < 8; nt++)
            #pragma unroll
            for (int i = 0; i < 4; i++) acc[mt][nt][i] = 0.0f;

    const int NC = K >> 5;
    issue(0); CP_COMMIT();
    issue(1); CP_COMMIT();

    for (int c = 0; c < NC; c++) {
        CP_WAIT1();
        __syncthreads();                    // single barrier per chunk
        if (c + 2 < NC) issue(c + 2);
        CP_COMMIT();

        const uint32_t stg = sbase + (c % 3) * STAGE_BYTES;

        #pragma unroll
        for (int ks = 0; ks < 4; ks++) {
            const int ca = 2 * ks + aCSel;
            const int cb = 2 * ks + bCSel;
            uint32_t a[4][4], b[8][2];
            #pragma unroll
            for (int mt = 0; mt < 4; mt++)
                ldsm_x4(a[mt], stg + aBase[mt] + (uint32_t)((ca ^ aPar[mt]) << 4));
            #pragma unroll
            for (int nt = 0; nt < 8; nt++)
                ldsm_x2(b[nt], stg + bBase[nt] + (uint32_t)((cb ^ bPar[nt]) << 4));
            #pragma unroll
            for (int mt = 0; mt < 4; mt++)
                #pragma unroll
                for (int nt = 0; nt < 8; nt++)
                    mma_tf32(acc[mt][nt], a[mt], b[nt]);
        }
    }

    #pragma unroll
    for (int mt = 0; mt < 4; mt++) {
        const int rm = blockIdx.y * 128 + m0w + mt * 16 + g;
        const float bv0 = (MBIAS == 1) ? __ldg(bias + rm)     : 0.0f;
        const float bv1 = (MBIAS == 1) ? __ldg(bias + rm + 8) : 0.0f;
        #pragma unroll
        for (int nt = 0; nt < 8; nt++) {
            const int cn = n0w + nt * 8 + t * 2;
            float cb0 = 0.0f, cb1 = 0.0f;
            if (MBIAS == 2) {
                const float* bb = bias + blockIdx.z * sBias + blockIdx.x * 128 + cn;
                cb0 = __ldg(bb);
                cb1 = __ldg(bb + 1);
            }
            float2 v0, v1;
            v0.x = alpha * acc[mt][nt][0] + bv0 + cb0;
            v0.y = alpha * acc[mt][nt][1] + bv0 + cb1;
            v1.x = alpha * acc[mt][nt][2] + bv1 + cb0;
            v1.y = alpha * acc[mt][nt][3] + bv1 + cb1;
            if (RND) {
                v0.x = rtf(v0.x); v0.y = rtf(v0.y);
                v1.x = rtf(v1.x); v1.y = rtf(v1.y);
            }
            const int r = m0w + mt * 16 + g;
            *reinterpret_cast<float2*>(&Cb[(size_t)r * ldc + cn]) = v0;
            *reinterpret_cast<float2*>(&Cb[(size_t)(r + 8) * ldc + cn]) = v1;
        }
    }
}

// ---------------------------------------------------------------------------
__global__ __launch_bounds__(256) void round_tf32(
    const float* __restrict__ in, float* __restrict__ out)
{
    const size_t i = (size_t)blockIdx.x * 256 + threadIdx.x;
    float4 v = reinterpret_cast<const float4*>(in)[i];
    v.x = rtf(v.x); v.y = rtf(v.y); v.z = rtf(v.z); v.w = rtf(v.w);
    reinterpret_cast<float4*>(out)[i] = v;
}

// ---------------------------------------------------------------------------
__global__ void transpose_rnd(const float* __restrict__ in, float* __restrict__ out,
                              int R, int C)
{
    __shared__ float tb[32][33];
    const int c0 = blockIdx.x * 32, r0 = blockIdx.y * 32;
    const int tx = threadIdx.x, ty = threadIdx.y;
    #pragma unroll
    for (int j = 0; j < 32; j += 8)
        tb[ty + j][tx] = in[(size_t)(r0 + ty + j) * C + c0 + tx];
    __syncthreads();
    #pragma unroll
    for (int j = 0; j < 32; j += 8)
        out[(size_t)(c0 + ty + j) * R + r0 + tx] = rtf(tb[tx][ty + j]);
}

// ---------------------------------------------------------------------------
__global__ void transpose_x(const float* __restrict__ in, float* __restrict__ out)
{
    __shared__ float tb[32][33];
    const int n0 = blockIdx.x * 32, c0 = blockIdx.y * 32;
    const float* ib = in  + (size_t)blockIdx.z * CIND * NTOK;
    float*       ob = out + (size_t)blockIdx.z * NTOK * CIND;
    const int tx = threadIdx.x, ty = threadIdx.y;
    #pragma unroll
    for (int j = 0; j < 32; j += 8)
        tb[ty + j][tx] = ib[(size_t)(c0 + ty + j) * NTOK + n0 + tx];
    __syncthreads();
    #pragma unroll
    for (int j = 0; j < 32; j += 8)
        ob[(size_t)(n0 + ty + j) * CIND + c0 + tx] = rtf(tb[tx][ty + j]);
}

// ---------------------------------------------------------------------------
__global__ __launch_bounds__(256) void gemv_bias(
    const float* __restrict__ W, const float* __restrict__ b, float* __restrict__ out)
{
    __shared__ float red[256];
    const int r = blockIdx.x;
    float s = 0.0f;
    for (int e = threadIdx.x; e < EMBD; e += 256)
        s += W[(size_t)r * EMBD + e] * b[e];
    red[threadIdx.x] = s;
    __syncthreads();
    for (int o = 128; o; o >>= 1) {
        if (threadIdx.x < o) red[threadIdx.x] += red[threadIdx.x + o];
        __syncthreads();
    }
    if (threadIdx.x == 0) out[r] = red[0];
}

// ---------------------------------------------------------------------------
__global__ __launch_bounds__(256) void beta_rows(
    const float* __restrict__ M, const float* __restrict__ v,
    float* __restrict__ beta, float scale)
{
    const int row = blockIdx.x * 8 + (threadIdx.x >> 5);
    const int lane = threadIdx.x & 31;
    const float* mr = M + (size_t)row * EMBD;
    float s = 0.0f;
    #pragma unroll 4
    for (int e = lane; e < EMBD; e += 32) s += mr[e] * v[e];
    #pragma unroll
    for (int o = 16; o; o >>= 1) s += __shfl_xor_sync(0xffffffffu, s, o);
    if (lane == 0) beta[row] = scale * s;
}

// ---------------------------------------------------------------------------
__global__ __launch_bounds__(256) void softmax_rows(
    float* __restrict__ S, float* __restrict__ SR,
    const unsigned char* __restrict__ mask)
{
    const size_t row = blockIdx.x;
    float4* p  = reinterpret_cast<float4*>(S  + row * SEQL);
    float4* pr = reinterpret_cast<float4*>(SR + row * SEQL);
    const uchar4* mp = reinterpret_cast<const uchar4*>(mask + row * SEQL);
    const int t = threadIdx.x;

    float4 v = p[t];
    uchar4 m = mp[t];
    if (m.x) v.x = -1e9f;
    if (m.y) v.y = -1e9f;
    if (m.z) v.z = -1e9f;
    if (m.w) v.w = -1e9f;

    float mx = fmaxf(fmaxf(v.x, v.y), fmaxf(v.z, v.w));
    #pragma unroll
    for (int o = 16; o; o >>= 1) mx = fmaxf(mx, __shfl_xor_sync(0xffffffffu, mx, o));
    __shared__ float sm[8];
    const int w = t >> 5;
    if ((t & 31) == 0) sm[w] = mx;
    __syncthreads();
    float rmax = sm[0];
    #pragma unroll
    for (int i = 1; i < 8; i++) rmax = fmaxf(rmax, sm[i]);

    v.x = __expf(v.x - rmax); v.y = __expf(v.y - rmax);
    v.z = __expf(v.z - rmax); v.w = __expf(v.w - rmax);

    float s = v.x + v.y + v.z + v.w;
    #pragma unroll
    for (int o = 16; o; o >>= 1) s += __shfl_xor_sync(0xffffffffu, s, o);
    __shared__ float ss[8];
    if ((t & 31) == 0) ss[w] = s;
    __syncthreads();
    float tot = 0.0f;
    #pragma unroll
    for (int i = 0; i < 8; i++) tot += ss[i];

    float inv = 1.0f / tot;
    v.x *= inv; v.y *= inv; v.z *= inv; v.w *= inv;
    p[t] = v;
    float4 r;
    r.x = rtf(v.x); r.y = rtf(v.y); r.z = rtf(v.z); r.w = rtf(v.w);
    pr[t] = r;
}

// ---------------------------------------------------------------------------
extern "C" void kernel_launch(void* const* d_in, const int* in_sizes, int n_in,
                              void* d_out, int out_size)
{
    const float* x       = (const float*)d_in[0];
    const float* content = (const float*)d_in[1];
    const unsigned char* pmask = (const unsigned char*)d_in[2];
    const float* W_in    = (const float*)d_in[3];
    const float* b_in    = (const float*)d_in[4];
    const float* Wq      = (const float*)d_in[5];
    const float* Wk      = (const float*)d_in[6];
    const float* Wv      = (const float*)d_in[7];
    const float* W_out   = (const float*)d_in[8];
    const float* b_out   = (const float*)d_in[9];

    float* out = (float*)d_out;                       // (8,512,32,32)
    float* att = out + (size_t)BATCH * CIND * NTOK;   // (8,1024,1024)

    float *xT, *Ct, *Zt, *beta, *aR, *Ut, *Wq2, *Wkt, *Wit, *WqiT, *Mz,
          *bq, *bk, *Wo2, *Wvt, *Wvo;
    cudaGetSymbolAddress((void**)&xT,   g_xT);
    cudaGetSymbolAddress((void**)&Ct,   g_Ct);
    cudaGetSymbolAddress((void**)&Zt,   g_Zt);
    cudaGetSymbolAddress((void**)&beta, g_beta);
    cudaGetSymbolAddress((void**)&aR,   g_aR);
    cudaGetSymbolAddress((void**)&Ut,   g_Ut);
    cudaGetSymbolAddress((void**)&Wq2,  g_Wq2);
    cudaGetSymbolAddress((void**)&Wkt,  g_Wkt);
    cudaGetSymbolAddress((void**)&Wit,  g_Wit);
    cudaGetSymbolAddress((void**)&WqiT, g_WqiT);
    cudaGetSymbolAddress((void**)&Mz,   g_Mz);
    cudaGetSymbolAddress((void**)&bq,   g_bq);
    cudaGetSymbolAddress((void**)&bk,   g_bk);
    cudaGetSymbolAddress((void**)&Wo2,  g_Wo2);
    cudaGetSymbolAddress((void**)&Wvt,  g_Wvt);
    cudaGetSymbolAddress((void**)&Wvo,  g_Wvo);

    cudaFuncSetAttribute(tc_gemm<0,1>, cudaFuncAttributeMaxDynamicSharedMemorySize, SMEM_BYTES);
    cudaFuncSetAttribute(tc_gemm<1,0>, cudaFuncAttributeMaxDynamicSharedMemorySize, SMEM_BYTES);
    cudaFuncSetAttribute(tc_gemm<2,0>, cudaFuncAttributeMaxDynamicSharedMemorySize, SMEM_BYTES);

    static cudaStream_t s1 = nullptr, s2 = nullptr, s3 = nullptr;
    static cudaEvent_t eF, eWkt, eCt, ebq, eMz, eXT, eBeta, eUt, eE1, eE2, eE3;
    if (s1 == nullptr) {
        cudaStreamCreateWithFlags(&s1, cudaStreamNonBlocking);
        cudaStreamCreateWithFlags(&s2, cudaStreamNonBlocking);
        cudaStreamCreateWithFlags(&s3, cudaStreamNonBlocking);
        cudaEventCreateWithFlags(&eF,    cudaEventDisableTiming);
        cudaEventCreateWithFlags(&eWkt,  cudaEventDisableTiming);
        cudaEventCreateWithFlags(&eCt,   cudaEventDisableTiming);
        cudaEventCreateWithFlags(&ebq,   cudaEventDisableTiming);
        cudaEventCreateWithFlags(&eMz,   cudaEventDisableTiming);
        cudaEventCreateWithFlags(&eXT,   cudaEventDisableTiming);
        cudaEventCreateWithFlags(&eBeta, cudaEventDisableTiming);
        cudaEventCreateWithFlags(&eUt,   cudaEventDisableTiming);
        cudaEventCreateWithFlags(&eE1,   cudaEventDisableTiming);
        cudaEventCreateWithFlags(&eE2,   cudaEventDisableTiming);
        cudaEventCreateWithFlags(&eE3,   cudaEventDisableTiming);
    }

    const size_t SE  = (size_t)SEQL * EMBD;
    const size_t NS  = (size_t)NTOK * SEQL;
    const size_t NSc = (size_t)SEQL * CIND;
    const size_t XC  = (size_t)NTOK * CIND;
    const size_t CS  = (size_t)CIND * SEQL;
    const size_t CN  = (size_t)CIND * NTOK;
    const float scale = 1.0f / 32.0f;

    // Capture legality: every cudaStreamWaitEvent is enqueued AFTER its
    // cudaEventRecord in host order.

    // ---- fork ----
    cudaEventRecord(eF, 0);
    cudaStreamWaitEvent(s1, eF, 0);
    cudaStreamWaitEvent(s2, eF, 0);
    cudaStreamWaitEvent(s3, eF, 0);

    // ======== prep phase ========
    // s1: Wk^T, content round
    transpose_rnd<<<dim3(EMBD / 32, EMBD / 32), dim3(32, 8), 0, s1>>>(Wk, Wkt, EMBD, EMBD);
    cudaEventRecord(eWkt, s1);
    round_tf32<<<(BATCH * SE) / 1024, 256, 0, s1>>>(content, Ct);
    cudaEventRecord(eCt, s1);

    // s0 (default): Wq round, bq, Wit, WqiT, Mz
    round_tf32<<<(EMBD * EMBD) / 1024, 256>>>(Wq, Wq2);
    gemv_bias<<<EMBD, 256>>>(Wq, b_in, bq);
    cudaEventRecord(ebq, 0);
    transpose_rnd<<<dim3(CIND / 32, EMBD / 32), dim3(32, 8)>>>(W_in, Wit, EMBD, CIND);
    tc_gemm<0,1><<<dim3(8, 4, 1), 128, SMEM_BYTES>>>(
        Wit, Wq2, WqiT, nullptr, EMBD, EMBD, 0, 0, 0, 0, 1.0f);
    cudaStreamWaitEvent(0, eWkt, 0);
    tc_gemm<0,1><<<dim3(8, 4, 1), 128, SMEM_BYTES>>>(
        WqiT, Wkt, Mz, nullptr, EMBD, EMBD, 0, 0, 0, 0, 1.0f);
    cudaEventRecord(eMz, 0);

    // s2: x transpose
    transpose_x<<<dim3(NTOK / 32, CIND / 32, BATCH), dim3(32, 8), 0, s2>>>(x, xT);
    cudaEventRecord(eXT, s2);

    // s3: W_out round, Wv^T, Wvo fold, Ut (all 8 batches)
    round_tf32<<<(CIND * EMBD) / 1024, 256, 0, s3>>>(W_out, Wo2);
    transpose_rnd<<<dim3(EMBD / 32, EMBD / 32), dim3(32, 8), 0, s3>>>(Wv, Wvt, EMBD, EMBD);
    tc_gemm<0,1><<<dim3(8, 4, 1), 128, SMEM_BYTES, s3>>>(
        Wo2, Wvt, Wvo, nullptr, EMBD, EMBD, 0, 0, 0, 0, 1.0f);
    cudaStreamWaitEvent(s3, eCt, 0);
    tc_gemm<0,1><<<dim3(8, 4, BATCH), 128, SMEM_BYTES, s3>>>(
        Wvo, Ct, Ut, nullptr, EMBD, SEQL, 0, SE, CS, 0, 1.0f);
    cudaEventRecord(eUt, s3);

    // s1 (cont.): bk, beta (all 8 batches)
    cudaStreamWaitEvent(s1, ebq, 0);
    gemv_bias<<<EMBD, 256, 0, s1>>>(Wkt, bq, bk);
    beta_rows<<<(BATCH * SEQL) / 8, 256, 0, s1>>>(Ct, bk, beta, scale);
    cudaEventRecord(eBeta, s1);

    // ======== pipelined tail: 4 quarters of QB=2 batches ========
    cudaStream_t qs[4] = { (cudaStream_t)0, s1, s2, s3 };
    for (int q = 0; q < 4; q++) {
        cudaStream_t S = qs[q];
        const size_t b0 = (size_t)(q * QB);
        // Zt_q = Ct_q · Mz  (needs Ct and Mz)
        if (q != 1) cudaStreamWaitEvent(S, eCt, 0);     // native on s1
        if (q != 0) cudaStreamWaitEvent(S, eMz, 0);     // native on default
        tc_gemm<0,1><<<dim3(4, 8, QB), 128, SMEM_BYTES, S>>>(
            Ct + b0 * SE, Mz, Zt + b0 * NSc, nullptr,
            EMBD, CIND, SE, 0, NSc, 0, 1.0f);
        // scores_q = scale·xT_q·Zt_q^T + beta_q  (needs xT, beta)
        if (q != 2) cudaStreamWaitEvent(S, eXT, 0);     // native on s2
        if (q != 1) cudaStreamWaitEvent(S, eBeta, 0);   // native on s1
        tc_gemm<2,0><<<dim3(8, 8, QB), 128, SMEM_BYTES, S>>>(
            xT + b0 * XC, Zt + b0 * NSc, att + b0 * NS, beta + b0 * SEQL,
            CIND, SEQL, XC, NSc, NS, SEQL, scale);
        softmax_rows<<<QB * NTOK, 256, 0, S>>>(
            att + b0 * NS, aR + b0 * NS, pmask + b0 * NS);
        // out_q = Ut_q·aR_q^T + b_out  (needs Ut)
        if (q != 3) cudaStreamWaitEvent(S, eUt, 0);     // native on s3
        tc_gemm<1,0><<<dim3(8, 4, QB), 128, SMEM_BYTES, S>>>(
            Ut + b0 * CS, aR + b0 * NS, out + b0 * CN, b_out,
            SEQL, NTOK, CS, NS, CN, 0, 1.0f);
    }

    // ---- join all side streams into default ----
    cudaEventRecord(eE1, s1);
    cudaEventRecord(eE2, s2);
    cudaEventRecord(eE3, s3);
    cudaStreamWaitEvent(0, eE1, 0);
    cudaStreamWaitEvent(0, eE2, 0);
    cudaStreamWaitEvent(0, eE3, 0);
}

// round 17
// speedup vs baseline: 1.2067x; 1.0701x over previous
#include <cuda_runtime.h>
#include <cstdint>

#define BATCH 8
#define QB    2                      // batches per quarter
#define EMBD  1024
#define CIND  512
#define NTOK  1024
#define SEQL  1024

// ---------------- scratch (device globals; allocation-free) ----------------
__device__ float g_xT [(size_t)BATCH * NTOK * CIND];  // x^T, tf32-rounded
__device__ float g_Ct [(size_t)BATCH * SEQL * EMBD];  // rounded content
__device__ float g_Zt [(size_t)BATCH * SEQL * CIND];  // Zt[s][c] = Ct·Mz (rounded)
__device__ float g_beta[(size_t)BATCH * SEQL];        // scale * Ct·bk  (fp32)
__device__ float g_aR [(size_t)BATCH * NTOK * SEQL];  // rounded copy of att
__device__ float g_Ut [(size_t)BATCH * CIND * SEQL];  // Ut[c][s]
__device__ float g_Wq2[EMBD * EMBD];                  // rounded Wq
__device__ float g_Wkt[EMBD * EMBD];                  // Wk^T rounded: [e][e']
__device__ float g_Wit[CIND * EMBD];                  // W_in^T rounded
__device__ float g_WqiT[CIND * EMBD];                 // (Wq·W_in)^T : [c][e']
__device__ float g_Mz [CIND * EMBD];                  // Mz[c][e] = Wqi^T·Wk
__device__ float g_bq [EMBD];                         // Wq·b_in (fp32)
__device__ float g_bk [EMBD];                         // Wk^T·bq (fp32)
__device__ float g_Wo2[CIND * EMBD];                  // rounded W_out
__device__ float g_Wvt[EMBD * EMBD];                  // Wv^T rounded
__device__ float g_Wvo[CIND * EMBD];                  // folded W_out·Wv

// ---------------- helpers ----------------
__device__ __forceinline__ uint32_t smem_u32(const void* p) {
    uint32_t a;
    asm("{ .reg .u64 t; cvta.to.shared.u64 t, %1; cvt.u32.u64 %0, t; }" : "=r"(a) : "l"(p));
    return a;
}
__device__ __forceinline__ uint32_t f2tf(float x) {
    uint32_t r; asm("cvt.rna.tf32.f32 %0, %1;" : "=r"(r) : "f"(x)); return r;
}
__device__ __forceinline__ float rtf(float x) { return __uint_as_float(f2tf(x)); }

#define CP_ASYNC16(dst, src) \
    asm volatile("cp.async.cg.shared.global.L2::128B [%0], [%1], 16;" \
                 :: "r"(dst), "l"(src) : "memory")
#define CP_COMMIT() asm volatile("cp.async.commit_group;" ::: "memory")
#define CP_WAIT1()  asm volatile("cp.async.wait_group 1;" ::: "memory")

__device__ __forceinline__ void ldsm_x4(uint32_t* r, uint32_t a) {
    asm volatile("ldmatrix.sync.aligned.m8n8.x4.shared.b16 {%0,%1,%2,%3}, [%4];"
                 : "=r"(r[0]), "=r"(r[1]), "=r"(r[2]), "=r"(r[3]) : "r"(a));
}
__device__ __forceinline__ void mma_tf32(float* d, const uint32_t* a, const uint32_t* b) {
    asm volatile(
        "mma.sync.aligned.m16n8k8.row.col.f32.tf32.tf32.f32 "
        "{%0,%1,%2,%3}, {%4,%5,%6,%7}, {%8,%9}, {%0,%1,%2,%3};"
        : "+f"(d[0]), "+f"(d[1]), "+f"(d[2]), "+f"(d[3])
        : "r"(a[0]), "r"(a[1]), "r"(a[2]), "r"(a[3]), "r"(b[0]), "r"(b[1]));
}

// ---------------------------------------------------------------------------
// TF32 tensor-core GEMM:  C[m][n] = alpha * sum_k A[m][k] * B[n][k] (+bias)
// A, B K-major, row stride == K, PRE-ROUNDED to tf32 in memory.
// Block tile 128x128, BK=32, 3-stage cp.async pipeline, 128 threads
// (4 warps 2x2, warp tile 64x64). Single barrier per K-chunk.
// B fragments packed via ldmatrix.x4 (lanes 0-15: nt-pair lo, 16-31: hi).
// MBIAS: 0 none, 1 row bias (per m), 2 batched col bias. RND: round C store.
// ---------------------------------------------------------------------------
#define STAGE_BYTES 32768
#define SMEM_BYTES  (3 * STAGE_BYTES)

template<int MBIAS, int RND>
__global__ __launch_bounds__(128, 2) void tc_gemm(
    const float* __restrict__ A, const float* __restrict__ B,
    float* __restrict__ C, const float* __restrict__ bias,
    int K, int ldc, size_t sA, size_t sB, size_t sC, size_t sBias, float alpha)
{
    extern __shared__ char smem[];
    const uint32_t sbase = smem_u32(smem);
    const int tid  = threadIdx.x;
    const int wid  = tid >> 5, lane = tid & 31;
    const int g = lane >> 2, t = lane & 3;
    const int m0w = (wid & 1) * 64;
    const int n0w = (wid >> 1) * 64;

    const float* Ab = A + blockIdx.z * sA + (size_t)(blockIdx.y * 128) * K;
    const float* Bb = B + blockIdx.z * sB + (size_t)(blockIdx.x * 128) * K;
    float*       Cb = C + blockIdx.z * sC + (size_t)(blockIdx.y * 128) * ldc
                        + blockIdx.x * 128;

    const int fr = tid >> 3;          // 0..15
    const int fq = tid & 7;

    auto issue = [&](int stage) {
        const uint32_t sa = sbase + (stage % 3) * STAGE_BYTES;
        const int k0 = stage * 32;
        #pragma unroll
        for (int i = 0; i < 8; i++) {
            const int r = fr + i * 16;
            const uint32_t dst = sa + r * 128 + ((fq ^ (r & 7)) << 4);
            CP_ASYNC16(dst, Ab + (size_t)r * K + k0 + fq * 4);
        }
        #pragma unroll
        for (int i = 0; i < 8; i++) {
            const int r = fr + i * 16;
            const uint32_t dst = sa + 16384 + r * 128 + ((fq ^ (r & 7)) << 4);
            CP_ASYNC16(dst, Bb + (size_t)r * K + k0 + fq * 4);
        }
    };

    // A ldmatrix bases (x4: 16 rows x 2 k-chunks)
    const int aRow8 = (lane & 7) + ((lane >> 3) & 1) * 8;
    const int aCSel = (lane >> 4) & 1;
    uint32_t aBase[4]; int aPar[4];
    #pragma unroll
    for (int mt = 0; mt < 4; mt++) {
        const int r = m0w + mt * 16 + aRow8;
        aBase[mt] = (uint32_t)r * 128;
        aPar[mt]  = r & 7;
    }
    // B ldmatrix bases (x4: pair of 8-row n-tiles x 2 k-chunks).
    // lanes 0-15 -> tile 2p (bit3 = k-chunk), lanes 16-31 -> tile 2p+1.
    const int bCSel = (lane >> 3) & 1;
    const int bSel2 = (lane >> 4) & 1;
    uint32_t bBase[4]; int bPar[4];
    #pragma unroll
    for (int p = 0; p < 4; p++) {
        const int r = n0w + (2 * p + bSel2) * 8 + (lane & 7);
        bBase[p] = 16384u + (uint32_t)r * 128;
        bPar[p]  = r & 7;
    }

    float acc[4][8][4];
    #pragma unroll
    for (int mt = 0; mt < 4; mt++)
        #pragma unroll
        for (int nt = 0; nt < 8; nt++)
            #pragma unroll
            for (int i = 0; i < 4; i++) acc[mt][nt][i] = 0.0f;

    const int NC = K >> 5;
    issue(0); CP_COMMIT();
    issue(1); CP_COMMIT();

    for (int c = 0; c < NC; c++) {
        CP_WAIT1();
        __syncthreads();                    // single barrier per chunk
        if (c + 2 < NC) issue(c + 2);
        CP_COMMIT();

        const uint32_t stg = sbase + (c % 3) * STAGE_BYTES;

        #pragma unroll
        for (int ks = 0; ks < 4; ks++) {
            const int ca = 2 * ks + aCSel;
            const int cb = 2 * ks + bCSel;
            uint32_t a[4][4], b[8][2];
            #pragma unroll
            for (int mt = 0; mt < 4; mt++)
                ldsm_x4(a[mt], stg + aBase[mt] + (uint32_t)((ca ^ aPar[mt]) << 4));
            #pragma unroll
            for (int p = 0; p < 4; p++) {
                uint32_t rb[4];
                ldsm_x4(rb, stg + bBase[p] + (uint32_t)((cb ^ bPar[p]) << 4));
                b[2 * p][0]     = rb[0];
                b[2 * p][1]     = rb[1];
                b[2 * p + 1][0] = rb[2];
                b[2 * p + 1][1] = rb[3];
            }
            #pragma unroll
            for (int mt = 0; mt < 4; mt++)
                #pragma unroll
                for (int nt = 0; nt < 8; nt++)
                    mma_tf32(acc[mt][nt], a[mt], b[nt]);
        }
    }

    #pragma unroll
    for (int mt = 0; mt < 4; mt++) {
        const int rm = blockIdx.y * 128 + m0w + mt * 16 + g;
        const float bv0 = (MBIAS == 1) ? __ldg(bias + rm)     : 0.0f;
        const float bv1 = (MBIAS == 1) ? __ldg(bias + rm + 8) : 0.0f;
        #pragma unroll
        for (int nt = 0; nt < 8; nt++) {
            const int cn = n0w + nt * 8 + t * 2;
            float cb0 = 0.0f, cb1 = 0.0f;
            if (MBIAS == 2) {
                const float* bb = bias + blockIdx.z * sBias + blockIdx.x * 128 + cn;
                cb0 = __ldg(bb);
                cb1 = __ldg(bb + 1);
            }
            float2 v0, v1;
            v0.x = alpha * acc[mt][nt][0] + bv0 + cb0;
            v0.y = alpha * acc[mt][nt][1] + bv0 + cb1;
            v1.x = alpha * acc[mt][nt][2] + bv1 + cb0;
            v1.y = alpha * acc[mt][nt][3] + bv1 + cb1;
            if (RND) {
                v0.x = rtf(v0.x); v0.y = rtf(v0.y);
                v1.x = rtf(v1.x); v1.y = rtf(v1.y);
            }
            const int r = m0w + mt * 16 + g;
            *reinterpret_cast<float2*>(&Cb[(size_t)r * ldc + cn]) = v0;
            *reinterpret_cast<float2*>(&Cb[(size_t)(r + 8) * ldc + cn]) = v1;
        }
    }
}

// ---------------------------------------------------------------------------
__global__ __launch_bounds__(256) void round_tf32(
    const float* __restrict__ in, float* __restrict__ out)
{
    const size_t i = (size_t)blockIdx.x * 256 + threadIdx.x;
    float4 v = reinterpret_cast<const float4*>(in)[i];
    v.x = rtf(v.x); v.y = rtf(v.y); v.z = rtf(v.z); v.w = rtf(v.w);
    reinterpret_cast<float4*>(out)[i] = v;
}

// ---------------------------------------------------------------------------
__global__ void transpose_rnd(const float* __restrict__ in, float* __restrict__ out,
                              int R, int C)
{
    __shared__ float tb[32][33];
    const int c0 = blockIdx.x * 32, r0 = blockIdx.y * 32;
    const int tx = threadIdx.x, ty = threadIdx.y;
    #pragma unroll
    for (int j = 0; j < 32; j += 8)
        tb[ty + j][tx] = in[(size_t)(r0 + ty + j) * C + c0 + tx];
    __syncthreads();
    #pragma unroll
    for (int j = 0; j < 32; j += 8)
        out[(size_t)(c0 + ty + j) * R + r0 + tx] = rtf(tb[tx][ty + j]);
}

// ---------------------------------------------------------------------------
__global__ void transpose_x(const float* __restrict__ in, float* __restrict__ out)
{
    __shared__ float tb[32][33];
    const int n0 = blockIdx.x * 32, c0 = blockIdx.y * 32;
    const float* ib = in  + (size_t)blockIdx.z * CIND * NTOK;
    float*       ob = out + (size_t)blockIdx.z * NTOK * CIND;
    const int tx = threadIdx.x, ty = threadIdx.y;
    #pragma unroll
    for (int j = 0; j < 32; j += 8)
        tb[ty + j][tx] = ib[(size_t)(c0 + ty + j) * NTOK + n0 + tx];
    __syncthreads();
    #pragma unroll
    for (int j = 0; j < 32; j += 8)
        ob[(size_t)(n0 + ty + j) * CIND + c0 + tx] = rtf(tb[tx][ty + j]);
}

// ---------------------------------------------------------------------------
__global__ __launch_bounds__(256) void gemv_bias(
    const float* __restrict__ W, const float* __restrict__ b, float* __restrict__ out)
{
    __shared__ float red[256];
    const int r = blockIdx.x;
    float s = 0.0f;
    for (int e = threadIdx.x; e < EMBD; e += 256)
        s += W[(size_t)r * EMBD + e] * b[e];
    red[threadIdx.x] = s;
    __syncthreads();
    for (int o = 128; o; o >>= 1) {
        if (threadIdx.x < o) red[threadIdx.x] += red[threadIdx.x + o];
        __syncthreads();
    }
    if (threadIdx.x == 0) out[r] = red[0];
}

// ---------------------------------------------------------------------------
__global__ __launch_bounds__(256) void beta_rows(
    const float* __restrict__ M, const float* __restrict__ v,
    float* __restrict__ beta, float scale)
{
    const int row = blockIdx.x * 8 + (threadIdx.x >> 5);
    const int lane = threadIdx.x & 31;
    const float* mr = M + (size_t)row * EMBD;
    float s = 0.0f;
    #pragma unroll 4
    for (int e = lane; e < EMBD; e += 32) s += mr[e] * v[e];
    #pragma unroll
    for (int o = 16; o; o >>= 1) s += __shfl_xor_sync(0xffffffffu, s, o);
    if (lane == 0) beta[row] = scale * s;
}

// ---------------------------------------------------------------------------
__global__ __launch_bounds__(256) void softmax_rows(
    float* __restrict__ S, float* __restrict__ SR,
    const unsigned char* __restrict__ mask)
{
    const size_t row = blockIdx.x;
    float4* p  = reinterpret_cast<float4*>(S  + row * SEQL);
    float4* pr = reinterpret_cast<float4*>(SR + row * SEQL);
    const uchar4* mp = reinterpret_cast<const uchar4*>(mask + row * SEQL);
    const int t = threadIdx.x;

    float4 v = p[t];
    uchar4 m = mp[t];
    if (m.x) v.x = -1e9f;
    if (m.y) v.y = -1e9f;
    if (m.z) v.z = -1e9f;
    if (m.w) v.w = -1e9f;

    float mx = fmaxf(fmaxf(v.x, v.y), fmaxf(v.z, v.w));
    #pragma unroll
    for (int o = 16; o; o >>= 1) mx = fmaxf(mx, __shfl_xor_sync(0xffffffffu, mx, o));
    __shared__ float sm[8];
    const int w = t >> 5;
    if ((t & 31) == 0) sm[w] = mx;
    __syncthreads();
    float rmax = sm[0];
    #pragma unroll
    for (int i = 1; i < 8; i++) rmax = fmaxf(rmax, sm[i]);

    v.x = __expf(v.x - rmax); v.y = __expf(v.y - rmax);
    v.z = __expf(v.z - rmax); v.w = __expf(v.w - rmax);

    float s = v.x + v.y + v.z + v.w;
    #pragma unroll
    for (int o = 16; o; o >>= 1) s += __shfl_xor_sync(0xffffffffu, s, o);
    __shared__ float ss[8];
    if ((t & 31) == 0) ss[w] = s;
    __syncthreads();
    float tot = 0.0f;
    #pragma unroll
    for (int i = 0; i < 8; i++) tot += ss[i];

    float inv = 1.0f / tot;
    v.x *= inv; v.y *= inv; v.z *= inv; v.w *= inv;
    p[t] = v;
    float4 r;
    r.x = rtf(v.x); r.y = rtf(v.y); r.z = rtf(v.z); r.w = rtf(v.w);
    pr[t] = r;
}

// ---------------------------------------------------------------------------
extern "C" void kernel_launch(void* const* d_in, const int* in_sizes, int n_in,
                              void* d_out, int out_size)
{
    const float* x       = (const float*)d_in[0];
    const float* content = (const float*)d_in[1];
    const unsigned char* pmask = (const unsigned char*)d_in[2];
    const float* W_in    = (const float*)d_in[3];
    const float* b_in    = (const float*)d_in[4];
    const float* Wq      = (const float*)d_in[5];
    const float* Wk      = (const float*)d_in[6];
    const float* Wv      = (const float*)d_in[7];
    const float* W_out   = (const float*)d_in[8];
    const float* b_out   = (const float*)d_in[9];

    float* out = (float*)d_out;                       // (8,512,32,32)
    float* att = out + (size_t)BATCH * CIND * NTOK;   // (8,1024,1024)

    float *xT, *Ct, *Zt, *beta, *aR, *Ut, *Wq2, *Wkt, *Wit, *WqiT, *Mz,
          *bq, *bk, *Wo2, *Wvt, *Wvo;
    cudaGetSymbolAddress((void**)&xT,   g_xT);
    cudaGetSymbolAddress((void**)&Ct,   g_Ct);
    cudaGetSymbolAddress((void**)&Zt,   g_Zt);
    cudaGetSymbolAddress((void**)&beta, g_beta);
    cudaGetSymbolAddress((void**)&aR,   g_aR);
    cudaGetSymbolAddress((void**)&Ut,   g_Ut);
    cudaGetSymbolAddress((void**)&Wq2,  g_Wq2);
    cudaGetSymbolAddress((void**)&Wkt,  g_Wkt);
    cudaGetSymbolAddress((void**)&Wit,  g_Wit);
    cudaGetSymbolAddress((void**)&WqiT, g_WqiT);
    cudaGetSymbolAddress((void**)&Mz,   g_Mz);
    cudaGetSymbolAddress((void**)&bq,   g_bq);
    cudaGetSymbolAddress((void**)&bk,   g_bk);
    cudaGetSymbolAddress((void**)&Wo2,  g_Wo2);
    cudaGetSymbolAddress((void**)&Wvt,  g_Wvt);
    cudaGetSymbolAddress((void**)&Wvo,  g_Wvo);

    cudaFuncSetAttribute(tc_gemm<0,1>, cudaFuncAttributeMaxDynamicSharedMemorySize, SMEM_BYTES);
    cudaFuncSetAttribute(tc_gemm<1,0>, cudaFuncAttributeMaxDynamicSharedMemorySize, SMEM_BYTES);
    cudaFuncSetAttribute(tc_gemm<2,0>, cudaFuncAttributeMaxDynamicSharedMemorySize, SMEM_BYTES);

    static cudaStream_t s1 = nullptr, s2 = nullptr, s3 = nullptr;
    static cudaEvent_t eF, eWkt, eCt, ebq, eMz, eXT, eBeta, eUt, eE1, eE2, eE3;
    if (s1 == nullptr) {
        cudaStreamCreateWithFlags(&s1, cudaStreamNonBlocking);
        cudaStreamCreateWithFlags(&s2, cudaStreamNonBlocking);
        cudaStreamCreateWithFlags(&s3, cudaStreamNonBlocking);
        cudaEventCreateWithFlags(&eF,    cudaEventDisableTiming);
        cudaEventCreateWithFlags(&eWkt,  cudaEventDisableTiming);
        cudaEventCreateWithFlags(&eCt,   cudaEventDisableTiming);
        cudaEventCreateWithFlags(&ebq,   cudaEventDisableTiming);
        cudaEventCreateWithFlags(&eMz,   cudaEventDisableTiming);
        cudaEventCreateWithFlags(&eXT,   cudaEventDisableTiming);
        cudaEventCreateWithFlags(&eBeta, cudaEventDisableTiming);
        cudaEventCreateWithFlags(&eUt,   cudaEventDisableTiming);
        cudaEventCreateWithFlags(&eE1,   cudaEventDisableTiming);
        cudaEventCreateWithFlags(&eE2,   cudaEventDisableTiming);
        cudaEventCreateWithFlags(&eE3,   cudaEventDisableTiming);
    }

    const size_t SE  = (size_t)SEQL * EMBD;
    const size_t NS  = (size_t)NTOK * SEQL;
    const size_t NSc = (size_t)SEQL * CIND;
    const size_t XC  = (size_t)NTOK * CIND;
    const size_t CS  = (size_t)CIND * SEQL;
    const size_t CN  = (size_t)CIND * NTOK;
    const float scale = 1.0f / 32.0f;

    // Capture legality: every cudaStreamWaitEvent is enqueued AFTER its
    // cudaEventRecord in host order.

    // ---- fork ----
    cudaEventRecord(eF, 0);
    cudaStreamWaitEvent(s1, eF, 0);
    cudaStreamWaitEvent(s2, eF, 0);
    cudaStreamWaitEvent(s3, eF, 0);

    // ======== prep phase ========
    // s1: Wk^T, content round
    transpose_rnd<<<dim3(EMBD / 32, EMBD / 32), dim3(32, 8), 0, s1>>>(Wk, Wkt, EMBD, EMBD);
    cudaEventRecord(eWkt, s1);
    round_tf32<<<(BATCH * SE) / 1024, 256, 0, s1>>>(content, Ct);
    cudaEventRecord(eCt, s1);

    // s0 (default): Wq round, bq, Wit, WqiT, Mz
    round_tf32<<<(EMBD * EMBD) / 1024, 256>>>(Wq, Wq2);
    gemv_bias<<<EMBD, 256>>>(Wq, b_in, bq);
    cudaEventRecord(ebq, 0);
    transpose_rnd<<<dim3(CIND / 32, EMBD / 32), dim3(32, 8)>>>(W_in, Wit, EMBD, CIND);
    tc_gemm<0,1><<<dim3(8, 4, 1), 128, SMEM_BYTES>>>(
        Wit, Wq2, WqiT, nullptr, EMBD, EMBD, 0, 0, 0, 0, 1.0f);
    cudaStreamWaitEvent(0, eWkt, 0);
    tc_gemm<0,1><<<dim3(8, 4, 1), 128, SMEM_BYTES>>>(
        WqiT, Wkt, Mz, nullptr, EMBD, EMBD, 0, 0, 0, 0, 1.0f);
    cudaEventRecord(eMz, 0);

    // s2: x transpose
    transpose_x<<<dim3(NTOK / 32, CIND / 32, BATCH), dim3(32, 8), 0, s2>>>(x, xT);
    cudaEventRecord(eXT, s2);

    // s3: W_out round, Wv^T, Wvo fold, Ut (all 8 batches)
    round_tf32<<<(CIND * EMBD) / 1024, 256, 0, s3>>>(W_out, Wo2);
    transpose_rnd<<<dim3(EMBD / 32, EMBD / 32), dim3(32, 8), 0, s3>>>(Wv, Wvt, EMBD, EMBD);
    tc_gemm<0,1><<<dim3(8, 4, 1), 128, SMEM_BYTES, s3>>>(
        Wo2, Wvt, Wvo, nullptr, EMBD, EMBD, 0, 0, 0, 0, 1.0f);
    cudaStreamWaitEvent(s3, eCt, 0);
    tc_gemm<0,1><<<dim3(8, 4, BATCH), 128, SMEM_BYTES, s3>>>(
        Wvo, Ct, Ut, nullptr, EMBD, SEQL, 0, SE, CS, 0, 1.0f);
    cudaEventRecord(eUt, s3);

    // s1 (cont.): bk, beta (all 8 batches)
    cudaStreamWaitEvent(s1, ebq, 0);
    gemv_bias<<<EMBD, 256, 0, s1>>>(Wkt, bq, bk);
    beta_rows<<<(BATCH * SEQL) / 8, 256, 0, s1>>>(Ct, bk, beta, scale);
    cudaEventRecord(eBeta, s1);

    // ======== pipelined tail: 4 quarters of QB=2 batches ========
    cudaStream_t qs[4] = { (cudaStream_t)0, s1, s2, s3 };
    for (int q = 0; q < 4; q++) {
        cudaStream_t S = qs[q];
        const size_t b0 = (size_t)(q * QB);
        // Zt_q = Ct_q · Mz  (needs Ct and Mz)
        if (q != 1) cudaStreamWaitEvent(S, eCt, 0);     // native on s1
        if (q != 0) cudaStreamWaitEvent(S, eMz, 0);     // native on default
        tc_gemm<0,1><<<dim3(4, 8, QB), 128, SMEM_BYTES, S>>>(
            Ct + b0 * SE, Mz, Zt + b0 * NSc, nullptr,
            EMBD, CIND, SE, 0, NSc, 0, 1.0f);
        // scores_q = scale·xT_q·Zt_q^T + beta_q  (needs xT, beta)
        if (q != 2) cudaStreamWaitEvent(S, eXT, 0);     // native on s2
        if (q != 1) cudaStreamWaitEvent(S, eBeta, 0);   // native on s1
        tc_gemm<2,0><<<dim3(8, 8, QB), 128, SMEM_BYTES, S>>>(
            xT + b0 * XC, Zt + b0 * NSc, att + b0 * NS, beta + b0 * SEQL,
            CIND, SEQL, XC, NSc, NS, SEQL, scale);
        softmax_rows<<<QB * NTOK, 256, 0, S>>>(
            att + b0 * NS, aR + b0 * NS, pmask + b0 * NS);
        // out_q = Ut_q·aR_q^T + b_out  (needs Ut)
        if (q != 3) cudaStreamWaitEvent(S, eUt, 0);     // native on s3
        tc_gemm<1,0><<<dim3(8, 4, QB), 128, SMEM_BYTES, S>>>(
            Ut + b0 * CS, aR + b0 * NS, out + b0 * CN, b_out,
            SEQL, NTOK, CS, NS, CN, 0, 1.0f);
    }

    // ---- join all side streams into default ----
    cudaEventRecord(eE1, s1);
    cudaEventRecord(eE2, s2);
    cudaEventRecord(eE3, s3);
    cudaStreamWaitEvent(0, eE1, 0);
    cudaStreamWaitEvent(0, eE2, 0);
    cudaStreamWaitEvent(0, eE3, 0);
}